// round 14
// baseline (speedup 1.0000x reference)
#include <cuda_runtime.h>
#include <cuda_bf16.h>
#include <cstdint>

// Problem constants
#define B_   2
#define T_   4096
#define D_   768
#define DO_  256
#define H_   4
#define DH_  64
#define W1_  7
#define W2_  15
#define TP_  (T_ + 2*W1_)       // 4110
#define ROWS_ (B_ * TP_)        // 8220
#define MTOT_ (ROWS_ + W2_)     // 8235
#define MPAD_ 8320              // 65 * 128
#define NQV_ 512

#define MT_ 128
#define NT_ 128
#define KC_ 32                  // k per chunk
#define NCHUNK_ (D_ / KC_)      // 24

// smem stage: swizzled 64B rows, 4 arrays x 8KB:
//   AH=0, AL=8192, BH=16384, BL=24576 ; stage = 32768, 3 stages
#define AH_OFF_ 0
#define AL_OFF_ 8192
#define BH_OFF_ 16384
#define BL_OFF_ 24576
#define STG_B_ 32768
#define NSTG_ 3
#define GSMEM_ (NSTG_ * STG_B_)   // 98304

// Scratch
__device__ float g_qv[ROWS_ * NQV_];
__device__ float g_pos[W2_ * NQV_];
__device__ __nv_bfloat16 g_ahi[MPAD_ * D_];
__device__ __nv_bfloat16 g_alo[MPAD_ * D_];
__device__ __nv_bfloat16 g_bhi[NQV_ * D_];
__device__ __nv_bfloat16 g_blo[NQV_ * D_];

// ---------------------------------------------------------------------------
__device__ __forceinline__ uint32_t smem_u32(const void* p) {
    uint32_t a;
    asm("{ .reg .u64 t; cvta.to.shared.u64 t, %1; cvt.u32.u64 %0, t; }"
        : "=r"(a) : "l"(p));
    return a;
}
#define CPA16(dst, src) \
    asm volatile("cp.async.ca.shared.global [%0], [%1], 16;" :: "r"(dst), "l"(src))
#define CPA_COMMIT() asm volatile("cp.async.commit_group;" ::: "memory")
#define CPA_WAIT(n)  asm volatile("cp.async.wait_group %0;" :: "n"(n) : "memory")
#define LDMX4(r0, r1, r2, r3, a) \
    asm volatile("ldmatrix.sync.aligned.m8n8.x4.shared.b16 {%0,%1,%2,%3}, [%4];" \
                 : "=r"(r0), "=r"(r1), "=r"(r2), "=r"(r3) : "r"(a))

__device__ __forceinline__ void mma_bf16(float* d, const uint32_t* a,
                                         const uint32_t* b) {
    asm volatile(
        "mma.sync.aligned.m16n8k16.row.col.f32.bf16.bf16.f32 "
        "{%0,%1,%2,%3}, {%4,%5,%6,%7}, {%8,%9}, {%0,%1,%2,%3};"
        : "+f"(d[0]), "+f"(d[1]), "+f"(d[2]), "+f"(d[3])
        : "r"(a[0]), "r"(a[1]), "r"(a[2]), "r"(a[3]), "r"(b[0]), "r"(b[1]));
}

// ---------------------------------------------------------------------------
// Prep: split weights AND activations (+pos, +zero pad) into bf16 hi/lo.
// ---------------------------------------------------------------------------
#define NWV_ (NQV_ * (D_ / 8))          // 49152
#define NAV_ (MPAD_ * (D_ / 8))         // 798720
__global__ void prep_kernel(const float* __restrict__ inputs,
                            const float* __restrict__ Wq,
                            const float* __restrict__ Wv,
                            const float* __restrict__ pos_emb) {
    int i = blockIdx.x * blockDim.x + threadIdx.x;
    const float* src = nullptr;
    __nv_bfloat16 *dhi, *dlo;
    size_t off;
    if (i < NWV_) {
        int n = i / (D_ / 8);
        int k8 = (i - n * (D_ / 8)) * 8;
        src = (n < DO_) ? Wq + (size_t)n * D_ + k8
                        : Wv + (size_t)(n - DO_) * D_ + k8;
        off = (size_t)n * D_ + k8;
        dhi = g_bhi; dlo = g_blo;
    } else if (i < NWV_ + NAV_) {
        int j = i - NWV_;
        int r = j / (D_ / 8);
        int k8 = (j - r * (D_ / 8)) * 8;
        off = (size_t)r * D_ + k8;
        dhi = g_ahi; dlo = g_alo;
        if (r < ROWS_) {
            int bb = r / TP_;
            int tp = r - bb * TP_;
            if (tp >= W1_ && tp < W1_ + T_)
                src = inputs + ((size_t)bb * T_ + (tp - W1_)) * D_ + k8;
        } else if (r < MTOT_) {
            src = pos_emb + (size_t)(r - ROWS_) * D_ + k8;
        }
    } else return;

    uint32_t hp[4], lp[4];
    if (src) {
        float4 f0 = *(const float4*)src;
        float4 f1 = *(const float4*)(src + 4);
        float v[8] = {f0.x, f0.y, f0.z, f0.w, f1.x, f1.y, f1.z, f1.w};
        #pragma unroll
        for (int e = 0; e < 4; e++) {
            __nv_bfloat16 h0 = __float2bfloat16(v[2*e]);
            __nv_bfloat16 h1 = __float2bfloat16(v[2*e+1]);
            __nv_bfloat16 l0 = __float2bfloat16(v[2*e]   - __bfloat162float(h0));
            __nv_bfloat16 l1 = __float2bfloat16(v[2*e+1] - __bfloat162float(h1));
            hp[e] = (uint32_t)__bfloat16_as_ushort(h0)
                  | ((uint32_t)__bfloat16_as_ushort(h1) << 16);
            lp[e] = (uint32_t)__bfloat16_as_ushort(l0)
                  | ((uint32_t)__bfloat16_as_ushort(l1) << 16);
        }
    } else {
        #pragma unroll
        for (int e = 0; e < 4; e++) { hp[e] = 0u; lp[e] = 0u; }
    }
    *(uint4*)(dhi + off) = make_uint4(hp[0], hp[1], hp[2], hp[3]);
    *(uint4*)(dlo + off) = make_uint4(lp[0], lp[1], lp[2], lp[3]);
}

// ---------------------------------------------------------------------------
// GEMM [8320,768] x [512,768]^T, 3-term bf16 split, HMMA (R6 structure).
// 3-stage cp.async pipeline, race-free: wait(1) -> sync -> issue(c+2).
// XOR-swizzled smem (row*64B, slot = (c16 ^ (row>>1)) & 3).
// ---------------------------------------------------------------------------
extern __shared__ __align__(128) char gsm[];

__global__ __launch_bounds__(256, 2) void gemm_mma_kernel(
    const float* __restrict__ bq, const float* __restrict__ bv)
{
    __shared__ float bias_s[NT_];
    const uint32_t smb = smem_u32(gsm);
    const int tid  = threadIdx.x;
    const int wid  = tid >> 5;
    const int lane = tid & 31;
    const int m0   = blockIdx.x * MT_;
    const int n0   = blockIdx.y * NT_;

    if (tid < NT_)
        bias_s[tid] = (n0 < DO_) ? bq[n0 + tid] : bv[n0 - DO_ + tid];

    // ---- loader: thread -> (row = tid>>2, c16 = tid&3) and (+64 rows)
    const int lrow = tid >> 2;
    const int lc16 = tid & 3;
    const int lsel = (tid >> 3) & 3;
    const uint32_t d0 = (uint32_t)lrow * 64 + (uint32_t)((lc16 ^ lsel) & 3) * 16;
    const uint32_t d1 = d0 + 64 * 64;

    const size_t aoff0 = (size_t)(m0 + lrow) * D_ + lc16 * 8;
    const size_t aoff1 = aoff0 + (size_t)64 * D_;
    const size_t boff0 = (size_t)(n0 + lrow) * D_ + lc16 * 8;
    const size_t boff1 = boff0 + (size_t)64 * D_;

    #define ISSUE_CHUNK(c, s) do {                                   \
        uint32_t st = smb + (s) * STG_B_;                            \
        int kk = (c) * KC_;                                          \
        CPA16(st + AH_OFF_ + d0, g_ahi + aoff0 + kk);                \
        CPA16(st + AH_OFF_ + d1, g_ahi + aoff1 + kk);                \
        CPA16(st + AL_OFF_ + d0, g_alo + aoff0 + kk);                \
        CPA16(st + AL_OFF_ + d1, g_alo + aoff1 + kk);                \
        CPA16(st + BH_OFF_ + d0, g_bhi + boff0 + kk);                \
        CPA16(st + BH_OFF_ + d1, g_bhi + boff1 + kk);                \
        CPA16(st + BL_OFF_ + d0, g_blo + boff0 + kk);                \
        CPA16(st + BL_OFF_ + d1, g_blo + boff1 + kk);                \
        CPA_COMMIT();                                                \
    } while (0)

    // ---- fragment address components
    const int mwarp = wid >> 2, nwarp = wid & 3;
    const int rowA = mwarp * 64 + (lane & 15);
    const int selA = (rowA >> 1) & 3;
    const int hiA  = lane >> 4;
    const uint32_t aRow = (uint32_t)rowA * 64;
    const uint32_t aS0  = (uint32_t)(((0 + hiA) ^ selA) & 3) * 16;
    const uint32_t aS1  = (uint32_t)(((2 + hiA) ^ selA) & 3) * 16;

    const int rowB = nwarp * 32 + (lane & 7) + ((lane >> 4) & 1) * 8;
    const int selB = (rowB >> 1) & 3;
    const int hiB  = (lane >> 3) & 1;
    const uint32_t bRow = (uint32_t)rowB * 64;
    const uint32_t bS0  = (uint32_t)(((0 + hiB) ^ selB) & 3) * 16;
    const uint32_t bS1  = (uint32_t)(((2 + hiB) ^ selB) & 3) * 16;

    float acc[4][4][4];
    #pragma unroll
    for (int mt = 0; mt < 4; mt++)
        #pragma unroll
        for (int nt = 0; nt < 4; nt++)
            #pragma unroll
            for (int e = 0; e < 4; e++) acc[mt][nt][e] = 0.f;

    ISSUE_CHUNK(0, 0);
    ISSUE_CHUNK(1, 1);

    int stg = 0;
    for (int c = 0; c < NCHUNK_; c++) {
        if (c < NCHUNK_ - 1) { CPA_WAIT(1); } else { CPA_WAIT(0); }
        __syncthreads();
        if (c + 2 < NCHUNK_) {
            int ns = stg + 2; if (ns >= NSTG_) ns -= NSTG_;
            ISSUE_CHUNK(c + 2, ns);
        }

        const uint32_t st = smb + stg * STG_B_;
        #pragma unroll
        for (int ks = 0; ks < 2; ks++) {
            const uint32_t aAdr = st + aRow + (ks ? aS1 : aS0);
            const uint32_t bAdr = st + bRow + (ks ? bS1 : bS0);

            uint32_t Ah[4][4], Bh[2][4], Al[4][4], Bl[2][4];
            #pragma unroll
            for (int mt = 0; mt < 4; mt++)
                LDMX4(Ah[mt][0], Ah[mt][1], Ah[mt][2], Ah[mt][3],
                      aAdr + AH_OFF_ + mt * 1024);
            #pragma unroll
            for (int pr = 0; pr < 2; pr++)
                LDMX4(Bh[pr][0], Bh[pr][1], Bh[pr][2], Bh[pr][3],
                      bAdr + BH_OFF_ + pr * 1024);
            #pragma unroll
            for (int mt = 0; mt < 4; mt++)
                #pragma unroll
                for (int nt = 0; nt < 4; nt++)
                    mma_bf16(acc[mt][nt], Ah[mt], &Bh[nt >> 1][(nt & 1) * 2]);

            #pragma unroll
            for (int mt = 0; mt < 4; mt++)
                LDMX4(Al[mt][0], Al[mt][1], Al[mt][2], Al[mt][3],
                      aAdr + AL_OFF_ + mt * 1024);
            #pragma unroll
            for (int mt = 0; mt < 4; mt++)
                #pragma unroll
                for (int nt = 0; nt < 4; nt++)
                    mma_bf16(acc[mt][nt], Al[mt], &Bh[nt >> 1][(nt & 1) * 2]);

            #pragma unroll
            for (int pr = 0; pr < 2; pr++)
                LDMX4(Bl[pr][0], Bl[pr][1], Bl[pr][2], Bl[pr][3],
                      bAdr + BL_OFF_ + pr * 1024);
            #pragma unroll
            for (int mt = 0; mt < 4; mt++)
                #pragma unroll
                for (int nt = 0; nt < 4; nt++)
                    mma_bf16(acc[mt][nt], Ah[mt], &Bl[nt >> 1][(nt & 1) * 2]);
        }
        if (++stg >= NSTG_) stg = 0;
    }

    // epilogue
    const int fg = lane >> 2;
    const int fc = (lane & 3) * 2;
    const int colbase = n0 + nwarp * 32;
    #pragma unroll
    for (int mt = 0; mt < 4; mt++) {
        #pragma unroll
        for (int rh = 0; rh < 2; rh++) {
            int r = m0 + mwarp * 64 + mt * 16 + fg + rh * 8;
            float* dst;
            bool add_bias;
            if (r < ROWS_) {
                dst = g_qv + (size_t)r * NQV_ + colbase;
                add_bias = true;
            } else if (r < MTOT_) {
                dst = g_pos + (size_t)(r - ROWS_) * NQV_ + colbase;
                add_bias = false;
            } else continue;
            #pragma unroll
            for (int nt = 0; nt < 4; nt++) {
                int cidx = nwarp * 32 + nt * 8 + fc;
                float2 o;
                o.x = acc[mt][nt][rh * 2];
                o.y = acc[mt][nt][rh * 2 + 1];
                if (add_bias) { o.x += bias_s[cidx]; o.y += bias_s[cidx + 1]; }
                *(float2*)(dst + nt * 8 + fc) = o;
            }
        }
    }
}

// ---------------------------------------------------------------------------
// Attn v3 (proven correct R13): block = 128 t for one (b,h) -> 256 blocks =
// single wave at 2 CTAs/SM. Warp covers 8 t per pass, 2 passes.
// Row stride 80 floats, dim-group stride 20 (conflict-free).
// ---------------------------------------------------------------------------
#define RST_ 80
#define NTB_ 128                              // t per block
#define NROW_ (NTB_ + 2 * W1_)                // 142 rows
#define ATT_SMEM_ ((NROW_ * RST_ * 2 + W2_ * RST_ * 2) * 4)   // 100480 B

extern __shared__ __align__(16) float asmf[];

__global__ __launch_bounds__(256, 2) void attn_kernel(float* __restrict__ out) {
    float* ks = asmf;
    float* vs = ks + NROW_ * RST_;
    float* pq = vs + NROW_ * RST_;
    float* pv = pq + W2_ * RST_;

    const int bx    = blockIdx.x;             // 0..255
    const int chunk = bx & 31;
    const int h     = (bx >> 5) & 3;
    const int b     = bx >> 7;
    const int t0    = chunk * NTB_;
    const int tid   = threadIdx.x;

    const size_t base_row = (size_t)b * TP_ + t0;

    for (int idx = tid; idx < NROW_ * 16; idx += 256) {
        int row = idx >> 4, c4 = idx & 15;
        int doff = row * RST_ + (c4 >> 2) * 20 + (c4 & 3) * 4;
        const float* src = g_qv + (base_row + row) * NQV_ + h * DH_ + c4 * 4;
        *(float4*)(ks + doff) = *(const float4*)src;
        *(float4*)(vs + doff) = *(const float4*)(src + DO_);
    }
    for (int idx = tid; idx < W2_ * 16; idx += 256) {
        int row = idx >> 4, c4 = idx & 15;
        int doff = row * RST_ + (c4 >> 2) * 20 + (c4 & 3) * 4;
        const float* src = g_pos + (size_t)row * NQV_ + h * DH_ + c4 * 4;
        *(float4*)(pq + doff) = *(const float4*)src;
        *(float4*)(pv + doff) = *(const float4*)(src + DO_);
    }
    __syncthreads();

    const int warp = tid >> 5;
    const int lane = tid & 31;
    const int tsub = lane >> 2;
    const int dg   = lane & 3;
    const int dgo  = dg * 20;

    #pragma unroll
    for (int pass = 0; pass < 2; pass++) {
        const int tl = warp * 16 + pass * 8 + tsub;   // 0..127

        float4 q[4];
        #pragma unroll
        for (int j = 0; j < 4; j++)
            q[j] = *(const float4*)(ks + (tl + W1_) * RST_ + dgo + j * 4);

        float4 a4[4];
        #pragma unroll
        for (int j = 0; j < 4; j++) a4[j] = make_float4(0.f, 0.f, 0.f, 0.f);

        #pragma unroll
        for (int w = 0; w < W2_; w++) {
            const float* kr = ks + (tl + w) * RST_ + dgo;
            const float* pr = pq + w * RST_ + dgo;
            float p0, p1, p2, p3;
            {
                float4 kv0 = *(const float4*)(kr);
                float4 pv0 = *(const float4*)(pr);
                p0 = q[0].x*(kv0.x+pv0.x) + q[0].y*(kv0.y+pv0.y)
                   + q[0].z*(kv0.z+pv0.z) + q[0].w*(kv0.w+pv0.w);
                float4 kv1 = *(const float4*)(kr + 4);
                float4 pv1 = *(const float4*)(pr + 4);
                p1 = q[1].x*(kv1.x+pv1.x) + q[1].y*(kv1.y+pv1.y)
                   + q[1].z*(kv1.z+pv1.z) + q[1].w*(kv1.w+pv1.w);
                float4 kv2 = *(const float4*)(kr + 8);
                float4 pv2 = *(const float4*)(pr + 8);
                p2 = q[2].x*(kv2.x+pv2.x) + q[2].y*(kv2.y+pv2.y)
                   + q[2].z*(kv2.z+pv2.z) + q[2].w*(kv2.w+pv2.w);
                float4 kv3 = *(const float4*)(kr + 12);
                float4 pv3 = *(const float4*)(pr + 12);
                p3 = q[3].x*(kv3.x+pv3.x) + q[3].y*(kv3.y+pv3.y)
                   + q[3].z*(kv3.z+pv3.z) + q[3].w*(kv3.w+pv3.w);
            }
            float p = (p0 + p1) + (p2 + p3);
            p += __shfl_xor_sync(0xffffffffu, p, 1);
            p += __shfl_xor_sync(0xffffffffu, p, 2);

            const float* vr = vs + (tl + w) * RST_ + dgo;
            const float* pw = pv + w * RST_ + dgo;
            #pragma unroll
            for (int j = 0; j < 4; j++) {
                float4 vv = *(const float4*)(vr + j * 4);
                float4 pp = *(const float4*)(pw + j * 4);
                a4[j].x += p * (vv.x + pp.x);
                a4[j].y += p * (vv.y + pp.y);
                a4[j].z += p * (vv.z + pp.z);
                a4[j].w += p * (vv.w + pp.w);
            }
        }

        const int t = t0 + tl;
        float* dst = out + ((size_t)b * T_ + t) * DO_ + h * DH_ + dg * 16;
        #pragma unroll
        for (int j = 0; j < 4; j++)
            *(float4*)(dst + j * 4) = a4[j];
    }
}

// ---------------------------------------------------------------------------
extern "C" void kernel_launch(void* const* d_in, const int* in_sizes, int n_in,
                              void* d_out, int out_size) {
    const float* inputs  = (const float*)d_in[0];
    const float* Wq      = (const float*)d_in[1];
    const float* bq      = (const float*)d_in[2];
    const float* Wv      = (const float*)d_in[3];
    const float* bv      = (const float*)d_in[4];
    const float* pos_emb = (const float*)d_in[5];
    float* out = (float*)d_out;

    cudaFuncSetAttribute(gemm_mma_kernel,
                         cudaFuncAttributeMaxDynamicSharedMemorySize, GSMEM_);
    cudaFuncSetAttribute(attn_kernel,
                         cudaFuncAttributeMaxDynamicSharedMemorySize, ATT_SMEM_);

    prep_kernel<<<(NWV_ + NAV_ + 255) / 256, 256>>>(inputs, Wq, Wv, pos_emb);

    dim3 ggrid(MPAD_ / MT_, NQV_ / NT_);
    gemm_mma_kernel<<<ggrid, 256, GSMEM_>>>(bq, bv);

    attn_kernel<<<B_ * H_ * (T_ / NTB_), 256, ATT_SMEM_>>>(out);
}

// round 15
// speedup vs baseline: 1.4012x; 1.4012x over previous
#include <cuda_runtime.h>
#include <cuda_bf16.h>
#include <cstdint>

// Problem constants
#define B_   2
#define T_   4096
#define D_   768
#define DO_  256
#define H_   4
#define DH_  64
#define W1_  7
#define W2_  15
#define TP_  (T_ + 2*W1_)       // 4110
#define ROWS_ (B_ * TP_)        // 8220
#define MTOT_ (ROWS_ + W2_)     // 8235
#define MPAD_ 8320              // 65 * 128
#define NQV_ 512

#define MT_ 128
#define NT_ 128
#define KC_ 32                  // k per chunk
#define NCHUNK_ (D_ / KC_)      // 24

// smem stage: swizzled 64B rows, 4 arrays x 8KB:
//   AH=0, AL=8192, BH=16384, BL=24576 ; stage = 32768, 3 stages
#define AH_OFF_ 0
#define AL_OFF_ 8192
#define BH_OFF_ 16384
#define BL_OFF_ 24576
#define STG_B_ 32768
#define NSTG_ 3
#define GSMEM_ (NSTG_ * STG_B_)   // 98304

// Scratch
__device__ float g_qv[ROWS_ * NQV_];
__device__ float g_pos[W2_ * NQV_];
__device__ __nv_bfloat16 g_ahi[MPAD_ * D_];
__device__ __nv_bfloat16 g_alo[MPAD_ * D_];
__device__ __nv_bfloat16 g_bhi[NQV_ * D_];
__device__ __nv_bfloat16 g_blo[NQV_ * D_];

// ---------------------------------------------------------------------------
__device__ __forceinline__ uint32_t smem_u32(const void* p) {
    uint32_t a;
    asm("{ .reg .u64 t; cvta.to.shared.u64 t, %1; cvt.u32.u64 %0, t; }"
        : "=r"(a) : "l"(p));
    return a;
}
#define CPA16(dst, src) \
    asm volatile("cp.async.ca.shared.global [%0], [%1], 16;" :: "r"(dst), "l"(src))
#define CPA_COMMIT() asm volatile("cp.async.commit_group;" ::: "memory")
#define CPA_WAIT(n)  asm volatile("cp.async.wait_group %0;" :: "n"(n) : "memory")
#define LDMX4(r0, r1, r2, r3, a) \
    asm volatile("ldmatrix.sync.aligned.m8n8.x4.shared.b16 {%0,%1,%2,%3}, [%4];" \
                 : "=r"(r0), "=r"(r1), "=r"(r2), "=r"(r3) : "r"(a))

__device__ __forceinline__ void mma_bf16(float* d, const uint32_t* a,
                                         const uint32_t* b) {
    asm volatile(
        "mma.sync.aligned.m16n8k16.row.col.f32.bf16.bf16.f32 "
        "{%0,%1,%2,%3}, {%4,%5,%6,%7}, {%8,%9}, {%0,%1,%2,%3};"
        : "+f"(d[0]), "+f"(d[1]), "+f"(d[2]), "+f"(d[3])
        : "r"(a[0]), "r"(a[1]), "r"(a[2]), "r"(a[3]), "r"(b[0]), "r"(b[1]));
}

// ---------------------------------------------------------------------------
// Prep: split weights AND activations (+pos, +zero pad) into bf16 hi/lo.
// ---------------------------------------------------------------------------
#define NWV_ (NQV_ * (D_ / 8))          // 49152
#define NAV_ (MPAD_ * (D_ / 8))         // 798720
__global__ void prep_kernel(const float* __restrict__ inputs,
                            const float* __restrict__ Wq,
                            const float* __restrict__ Wv,
                            const float* __restrict__ pos_emb) {
    int i = blockIdx.x * blockDim.x + threadIdx.x;
    const float* src = nullptr;
    __nv_bfloat16 *dhi, *dlo;
    size_t off;
    if (i < NWV_) {
        int n = i / (D_ / 8);
        int k8 = (i - n * (D_ / 8)) * 8;
        src = (n < DO_) ? Wq + (size_t)n * D_ + k8
                        : Wv + (size_t)(n - DO_) * D_ + k8;
        off = (size_t)n * D_ + k8;
        dhi = g_bhi; dlo = g_blo;
    } else if (i < NWV_ + NAV_) {
        int j = i - NWV_;
        int r = j / (D_ / 8);
        int k8 = (j - r * (D_ / 8)) * 8;
        off = (size_t)r * D_ + k8;
        dhi = g_ahi; dlo = g_alo;
        if (r < ROWS_) {
            int bb = r / TP_;
            int tp = r - bb * TP_;
            if (tp >= W1_ && tp < W1_ + T_)
                src = inputs + ((size_t)bb * T_ + (tp - W1_)) * D_ + k8;
        } else if (r < MTOT_) {
            src = pos_emb + (size_t)(r - ROWS_) * D_ + k8;
        }
    } else return;

    uint32_t hp[4], lp[4];
    if (src) {
        float4 f0 = *(const float4*)src;
        float4 f1 = *(const float4*)(src + 4);
        float v[8] = {f0.x, f0.y, f0.z, f0.w, f1.x, f1.y, f1.z, f1.w};
        #pragma unroll
        for (int e = 0; e < 4; e++) {
            __nv_bfloat16 h0 = __float2bfloat16(v[2*e]);
            __nv_bfloat16 h1 = __float2bfloat16(v[2*e+1]);
            __nv_bfloat16 l0 = __float2bfloat16(v[2*e]   - __bfloat162float(h0));
            __nv_bfloat16 l1 = __float2bfloat16(v[2*e+1] - __bfloat162float(h1));
            hp[e] = (uint32_t)__bfloat16_as_ushort(h0)
                  | ((uint32_t)__bfloat16_as_ushort(h1) << 16);
            lp[e] = (uint32_t)__bfloat16_as_ushort(l0)
                  | ((uint32_t)__bfloat16_as_ushort(l1) << 16);
        }
    } else {
        #pragma unroll
        for (int e = 0; e < 4; e++) { hp[e] = 0u; lp[e] = 0u; }
    }
    *(uint4*)(dhi + off) = make_uint4(hp[0], hp[1], hp[2], hp[3]);
    *(uint4*)(dlo + off) = make_uint4(lp[0], lp[1], lp[2], lp[3]);
}

// ---------------------------------------------------------------------------
// GEMM [8320,768] x [512,768]^T, 3-term bf16 split, HMMA (R6 structure).
// 3-stage cp.async pipeline, race-free: wait(1) -> sync -> issue(c+2).
// XOR-swizzled smem (row*64B, slot = (c16 ^ (row>>1)) & 3).
// ---------------------------------------------------------------------------
extern __shared__ __align__(128) char gsm[];

__global__ __launch_bounds__(256, 2) void gemm_mma_kernel(
    const float* __restrict__ bq, const float* __restrict__ bv)
{
    __shared__ float bias_s[NT_];
    const uint32_t smb = smem_u32(gsm);
    const int tid  = threadIdx.x;
    const int wid  = tid >> 5;
    const int lane = tid & 31;
    const int m0   = blockIdx.x * MT_;
    const int n0   = blockIdx.y * NT_;

    if (tid < NT_)
        bias_s[tid] = (n0 < DO_) ? bq[n0 + tid] : bv[n0 - DO_ + tid];

    // ---- loader: thread -> (row = tid>>2, c16 = tid&3) and (+64 rows)
    const int lrow = tid >> 2;
    const int lc16 = tid & 3;
    const int lsel = (tid >> 3) & 3;
    const uint32_t d0 = (uint32_t)lrow * 64 + (uint32_t)((lc16 ^ lsel) & 3) * 16;
    const uint32_t d1 = d0 + 64 * 64;

    const size_t aoff0 = (size_t)(m0 + lrow) * D_ + lc16 * 8;
    const size_t aoff1 = aoff0 + (size_t)64 * D_;
    const size_t boff0 = (size_t)(n0 + lrow) * D_ + lc16 * 8;
    const size_t boff1 = boff0 + (size_t)64 * D_;

    #define ISSUE_CHUNK(c, s) do {                                   \
        uint32_t st = smb + (s) * STG_B_;                            \
        int kk = (c) * KC_;                                          \
        CPA16(st + AH_OFF_ + d0, g_ahi + aoff0 + kk);                \
        CPA16(st + AH_OFF_ + d1, g_ahi + aoff1 + kk);                \
        CPA16(st + AL_OFF_ + d0, g_alo + aoff0 + kk);                \
        CPA16(st + AL_OFF_ + d1, g_alo + aoff1 + kk);                \
        CPA16(st + BH_OFF_ + d0, g_bhi + boff0 + kk);                \
        CPA16(st + BH_OFF_ + d1, g_bhi + boff1 + kk);                \
        CPA16(st + BL_OFF_ + d0, g_blo + boff0 + kk);                \
        CPA16(st + BL_OFF_ + d1, g_blo + boff1 + kk);                \
        CPA_COMMIT();                                                \
    } while (0)

    // ---- fragment address components
    const int mwarp = wid >> 2, nwarp = wid & 3;
    const int rowA = mwarp * 64 + (lane & 15);
    const int selA = (rowA >> 1) & 3;
    const int hiA  = lane >> 4;
    const uint32_t aRow = (uint32_t)rowA * 64;
    const uint32_t aS0  = (uint32_t)(((0 + hiA) ^ selA) & 3) * 16;
    const uint32_t aS1  = (uint32_t)(((2 + hiA) ^ selA) & 3) * 16;

    const int rowB = nwarp * 32 + (lane & 7) + ((lane >> 4) & 1) * 8;
    const int selB = (rowB >> 1) & 3;
    const int hiB  = (lane >> 3) & 1;
    const uint32_t bRow = (uint32_t)rowB * 64;
    const uint32_t bS0  = (uint32_t)(((0 + hiB) ^ selB) & 3) * 16;
    const uint32_t bS1  = (uint32_t)(((2 + hiB) ^ selB) & 3) * 16;

    float acc[4][4][4];
    #pragma unroll
    for (int mt = 0; mt < 4; mt++)
        #pragma unroll
        for (int nt = 0; nt < 4; nt++)
            #pragma unroll
            for (int e = 0; e < 4; e++) acc[mt][nt][e] = 0.f;

    ISSUE_CHUNK(0, 0);
    ISSUE_CHUNK(1, 1);

    int stg = 0;
    for (int c = 0; c < NCHUNK_; c++) {
        if (c < NCHUNK_ - 1) { CPA_WAIT(1); } else { CPA_WAIT(0); }
        __syncthreads();
        if (c + 2 < NCHUNK_) {
            int ns = stg + 2; if (ns >= NSTG_) ns -= NSTG_;
            ISSUE_CHUNK(c + 2, ns);
        }

        const uint32_t st = smb + stg * STG_B_;
        #pragma unroll
        for (int ks = 0; ks < 2; ks++) {
            const uint32_t aAdr = st + aRow + (ks ? aS1 : aS0);
            const uint32_t bAdr = st + bRow + (ks ? bS1 : bS0);

            uint32_t Ah[4][4], Bh[2][4], Al[4][4], Bl[2][4];
            #pragma unroll
            for (int mt = 0; mt < 4; mt++)
                LDMX4(Ah[mt][0], Ah[mt][1], Ah[mt][2], Ah[mt][3],
                      aAdr + AH_OFF_ + mt * 1024);
            #pragma unroll
            for (int pr = 0; pr < 2; pr++)
                LDMX4(Bh[pr][0], Bh[pr][1], Bh[pr][2], Bh[pr][3],
                      bAdr + BH_OFF_ + pr * 1024);
            #pragma unroll
            for (int mt = 0; mt < 4; mt++)
                #pragma unroll
                for (int nt = 0; nt < 4; nt++)
                    mma_bf16(acc[mt][nt], Ah[mt], &Bh[nt >> 1][(nt & 1) * 2]);

            #pragma unroll
            for (int mt = 0; mt < 4; mt++)
                LDMX4(Al[mt][0], Al[mt][1], Al[mt][2], Al[mt][3],
                      aAdr + AL_OFF_ + mt * 1024);
            #pragma unroll
            for (int mt = 0; mt < 4; mt++)
                #pragma unroll
                for (int nt = 0; nt < 4; nt++)
                    mma_bf16(acc[mt][nt], Al[mt], &Bh[nt >> 1][(nt & 1) * 2]);

            #pragma unroll
            for (int pr = 0; pr < 2; pr++)
                LDMX4(Bl[pr][0], Bl[pr][1], Bl[pr][2], Bl[pr][3],
                      bAdr + BL_OFF_ + pr * 1024);
            #pragma unroll
            for (int mt = 0; mt < 4; mt++)
                #pragma unroll
                for (int nt = 0; nt < 4; nt++)
                    mma_bf16(acc[mt][nt], Ah[mt], &Bl[nt >> 1][(nt & 1) * 2]);
        }
        if (++stg >= NSTG_) stg = 0;
    }

    // epilogue
    const int fg = lane >> 2;
    const int fc = (lane & 3) * 2;
    const int colbase = n0 + nwarp * 32;
    #pragma unroll
    for (int mt = 0; mt < 4; mt++) {
        #pragma unroll
        for (int rh = 0; rh < 2; rh++) {
            int r = m0 + mwarp * 64 + mt * 16 + fg + rh * 8;
            float* dst;
            bool add_bias;
            if (r < ROWS_) {
                dst = g_qv + (size_t)r * NQV_ + colbase;
                add_bias = true;
            } else if (r < MTOT_) {
                dst = g_pos + (size_t)(r - ROWS_) * NQV_ + colbase;
                add_bias = false;
            } else continue;
            #pragma unroll
            for (int nt = 0; nt < 4; nt++) {
                int cidx = nwarp * 32 + nt * 8 + fc;
                float2 o;
                o.x = acc[mt][nt][rh * 2];
                o.y = acc[mt][nt][rh * 2 + 1];
                if (add_bias) { o.x += bias_s[cidx]; o.y += bias_s[cidx + 1]; }
                *(float2*)(dst + nt * 8 + fc) = o;
            }
        }
    }
}

// ---------------------------------------------------------------------------
// Attn v3b: block = 128 t for one (b,h) -> 256 blocks = single wave at
// 2 CTAs/SM (smem-limited). NO min-blocks launch bound: the (256,2) clause in
// R13/R14 capped regs at 128 and spilled the unrolled body (+38us).
// ---------------------------------------------------------------------------
#define RST_ 80
#define NTB_ 128                              // t per block
#define NROW_ (NTB_ + 2 * W1_)                // 142 rows
#define ATT_SMEM_ ((NROW_ * RST_ * 2 + W2_ * RST_ * 2) * 4)   // 100480 B

extern __shared__ __align__(16) float asmf[];

__global__ __launch_bounds__(256) void attn_kernel(float* __restrict__ out) {
    float* ks = asmf;
    float* vs = ks + NROW_ * RST_;
    float* pq = vs + NROW_ * RST_;
    float* pv = pq + W2_ * RST_;

    const int bx    = blockIdx.x;             // 0..255
    const int chunk = bx & 31;
    const int h     = (bx >> 5) & 3;
    const int b     = bx >> 7;
    const int t0    = chunk * NTB_;
    const int tid   = threadIdx.x;

    const size_t base_row = (size_t)b * TP_ + t0;

    for (int idx = tid; idx < NROW_ * 16; idx += 256) {
        int row = idx >> 4, c4 = idx & 15;
        int doff = row * RST_ + (c4 >> 2) * 20 + (c4 & 3) * 4;
        const float* src = g_qv + (base_row + row) * NQV_ + h * DH_ + c4 * 4;
        *(float4*)(ks + doff) = *(const float4*)src;
        *(float4*)(vs + doff) = *(const float4*)(src + DO_);
    }
    for (int idx = tid; idx < W2_ * 16; idx += 256) {
        int row = idx >> 4, c4 = idx & 15;
        int doff = row * RST_ + (c4 >> 2) * 20 + (c4 & 3) * 4;
        const float* src = g_pos + (size_t)row * NQV_ + h * DH_ + c4 * 4;
        *(float4*)(pq + doff) = *(const float4*)src;
        *(float4*)(pv + doff) = *(const float4*)(src + DO_);
    }
    __syncthreads();

    const int warp = tid >> 5;
    const int lane = tid & 31;
    const int tsub = lane >> 2;
    const int dg   = lane & 3;
    const int dgo  = dg * 20;

    for (int pass = 0; pass < 2; pass++) {
        const int tl = warp * 16 + pass * 8 + tsub;   // 0..127

        float4 q[4];
        #pragma unroll
        for (int j = 0; j < 4; j++)
            q[j] = *(const float4*)(ks + (tl + W1_) * RST_ + dgo + j * 4);

        float4 a4[4];
        #pragma unroll
        for (int j = 0; j < 4; j++) a4[j] = make_float4(0.f, 0.f, 0.f, 0.f);

        #pragma unroll
        for (int w = 0; w < W2_; w++) {
            const float* kr = ks + (tl + w) * RST_ + dgo;
            const float* pr = pq + w * RST_ + dgo;
            float p0, p1, p2, p3;
            {
                float4 kv0 = *(const float4*)(kr);
                float4 pv0 = *(const float4*)(pr);
                p0 = q[0].x*(kv0.x+pv0.x) + q[0].y*(kv0.y+pv0.y)
                   + q[0].z*(kv0.z+pv0.z) + q[0].w*(kv0.w+pv0.w);
                float4 kv1 = *(const float4*)(kr + 4);
                float4 pv1 = *(const float4*)(pr + 4);
                p1 = q[1].x*(kv1.x+pv1.x) + q[1].y*(kv1.y+pv1.y)
                   + q[1].z*(kv1.z+pv1.z) + q[1].w*(kv1.w+pv1.w);
                float4 kv2 = *(const float4*)(kr + 8);
                float4 pv2 = *(const float4*)(pr + 8);
                p2 = q[2].x*(kv2.x+pv2.x) + q[2].y*(kv2.y+pv2.y)
                   + q[2].z*(kv2.z+pv2.z) + q[2].w*(kv2.w+pv2.w);
                float4 kv3 = *(const float4*)(kr + 12);
                float4 pv3 = *(const float4*)(pr + 12);
                p3 = q[3].x*(kv3.x+pv3.x) + q[3].y*(kv3.y+pv3.y)
                   + q[3].z*(kv3.z+pv3.z) + q[3].w*(kv3.w+pv3.w);
            }
            float p = (p0 + p1) + (p2 + p3);
            p += __shfl_xor_sync(0xffffffffu, p, 1);
            p += __shfl_xor_sync(0xffffffffu, p, 2);

            const float* vr = vs + (tl + w) * RST_ + dgo;
            const float* pw = pv + w * RST_ + dgo;
            #pragma unroll
            for (int j = 0; j < 4; j++) {
                float4 vv = *(const float4*)(vr + j * 4);
                float4 pp = *(const float4*)(pw + j * 4);
                a4[j].x += p * (vv.x + pp.x);
                a4[j].y += p * (vv.y + pp.y);
                a4[j].z += p * (vv.z + pp.z);
                a4[j].w += p * (vv.w + pp.w);
            }
        }

        const int t = t0 + tl;
        float* dst = out + ((size_t)b * T_ + t) * DO_ + h * DH_ + dg * 16;
        #pragma unroll
        for (int j = 0; j < 4; j++)
            *(float4*)(dst + j * 4) = a4[j];
    }
}

// ---------------------------------------------------------------------------
extern "C" void kernel_launch(void* const* d_in, const int* in_sizes, int n_in,
                              void* d_out, int out_size) {
    const float* inputs  = (const float*)d_in[0];
    const float* Wq      = (const float*)d_in[1];
    const float* bq      = (const float*)d_in[2];
    const float* Wv      = (const float*)d_in[3];
    const float* bv      = (const float*)d_in[4];
    const float* pos_emb = (const float*)d_in[5];
    float* out = (float*)d_out;

    cudaFuncSetAttribute(gemm_mma_kernel,
                         cudaFuncAttributeMaxDynamicSharedMemorySize, GSMEM_);
    cudaFuncSetAttribute(attn_kernel,
                         cudaFuncAttributeMaxDynamicSharedMemorySize, ATT_SMEM_);

    prep_kernel<<<(NWV_ + NAV_ + 255) / 256, 256>>>(inputs, Wq, Wv, pos_emb);

    dim3 ggrid(MPAD_ / MT_, NQV_ / NT_);
    gemm_mma_kernel<<<ggrid, 256, GSMEM_>>>(bq, bv);

    attn_kernel<<<B_ * H_ * (T_ / NTB_), 256, ATT_SMEM_>>>(out);
}

// round 16
// speedup vs baseline: 1.4756x; 1.0531x over previous
#include <cuda_runtime.h>
#include <cuda_bf16.h>
#include <cstdint>

// Problem constants
#define B_   2
#define T_   4096
#define D_   768
#define DO_  256
#define H_   4
#define DH_  64
#define W1_  7
#define W2_  15
#define TP_  (T_ + 2*W1_)       // 4110
#define ROWS_ (B_ * TP_)        // 8220
#define MTOT_ (ROWS_ + W2_)     // 8235
#define MPAD_ 8320              // 65 * 128
#define NQV_ 512

#define MT_ 128
#define NT_ 128
#define KC_ 32                  // k per chunk
#define NCHUNK_ (D_ / KC_)      // 24

// smem stage: swizzled 64B rows, 4 arrays x 8KB:
//   AH=0, AL=8192, BH=16384, BL=24576 ; stage = 32768, 3 stages
#define AH_OFF_ 0
#define AL_OFF_ 8192
#define BH_OFF_ 16384
#define BL_OFF_ 24576
#define STG_B_ 32768
#define NSTG_ 3
#define GSMEM_ (NSTG_ * STG_B_)   // 98304

// Scratch
__device__ float g_qv[ROWS_ * NQV_];
__device__ float g_pos[W2_ * NQV_];
__device__ __nv_bfloat16 g_ahi[MPAD_ * D_];
__device__ __nv_bfloat16 g_alo[MPAD_ * D_];
__device__ __nv_bfloat16 g_bhi[NQV_ * D_];
__device__ __nv_bfloat16 g_blo[NQV_ * D_];

// ---------------------------------------------------------------------------
__device__ __forceinline__ uint32_t smem_u32(const void* p) {
    uint32_t a;
    asm("{ .reg .u64 t; cvta.to.shared.u64 t, %1; cvt.u32.u64 %0, t; }"
        : "=r"(a) : "l"(p));
    return a;
}
#define CPA16(dst, src) \
    asm volatile("cp.async.ca.shared.global [%0], [%1], 16;" :: "r"(dst), "l"(src))
#define CPA_COMMIT() asm volatile("cp.async.commit_group;" ::: "memory")
#define CPA_WAIT(n)  asm volatile("cp.async.wait_group %0;" :: "n"(n) : "memory")
#define LDMX4(r0, r1, r2, r3, a) \
    asm volatile("ldmatrix.sync.aligned.m8n8.x4.shared.b16 {%0,%1,%2,%3}, [%4];" \
                 : "=r"(r0), "=r"(r1), "=r"(r2), "=r"(r3) : "r"(a))

__device__ __forceinline__ void mma_bf16(float* d, const uint32_t* a,
                                         const uint32_t* b) {
    asm volatile(
        "mma.sync.aligned.m16n8k16.row.col.f32.bf16.bf16.f32 "
        "{%0,%1,%2,%3}, {%4,%5,%6,%7}, {%8,%9}, {%0,%1,%2,%3};"
        : "+f"(d[0]), "+f"(d[1]), "+f"(d[2]), "+f"(d[3])
        : "r"(a[0]), "r"(a[1]), "r"(a[2]), "r"(a[3]), "r"(b[0]), "r"(b[1]));
}

// ---------------------------------------------------------------------------
// Prep: split weights AND activations (+pos, +zero pad) into bf16 hi/lo.
// ---------------------------------------------------------------------------
#define NWV_ (NQV_ * (D_ / 8))          // 49152
#define NAV_ (MPAD_ * (D_ / 8))         // 798720
__global__ void prep_kernel(const float* __restrict__ inputs,
                            const float* __restrict__ Wq,
                            const float* __restrict__ Wv,
                            const float* __restrict__ pos_emb) {
    int i = blockIdx.x * blockDim.x + threadIdx.x;
    const float* src = nullptr;
    __nv_bfloat16 *dhi, *dlo;
    size_t off;
    if (i < NWV_) {
        int n = i / (D_ / 8);
        int k8 = (i - n * (D_ / 8)) * 8;
        src = (n < DO_) ? Wq + (size_t)n * D_ + k8
                        : Wv + (size_t)(n - DO_) * D_ + k8;
        off = (size_t)n * D_ + k8;
        dhi = g_bhi; dlo = g_blo;
    } else if (i < NWV_ + NAV_) {
        int j = i - NWV_;
        int r = j / (D_ / 8);
        int k8 = (j - r * (D_ / 8)) * 8;
        off = (size_t)r * D_ + k8;
        dhi = g_ahi; dlo = g_alo;
        if (r < ROWS_) {
            int bb = r / TP_;
            int tp = r - bb * TP_;
            if (tp >= W1_ && tp < W1_ + T_)
                src = inputs + ((size_t)bb * T_ + (tp - W1_)) * D_ + k8;
        } else if (r < MTOT_) {
            src = pos_emb + (size_t)(r - ROWS_) * D_ + k8;
        }
    } else return;

    uint32_t hp[4], lp[4];
    if (src) {
        float4 f0 = *(const float4*)src;
        float4 f1 = *(const float4*)(src + 4);
        float v[8] = {f0.x, f0.y, f0.z, f0.w, f1.x, f1.y, f1.z, f1.w};
        #pragma unroll
        for (int e = 0; e < 4; e++) {
            __nv_bfloat16 h0 = __float2bfloat16(v[2*e]);
            __nv_bfloat16 h1 = __float2bfloat16(v[2*e+1]);
            __nv_bfloat16 l0 = __float2bfloat16(v[2*e]   - __bfloat162float(h0));
            __nv_bfloat16 l1 = __float2bfloat16(v[2*e+1] - __bfloat162float(h1));
            hp[e] = (uint32_t)__bfloat16_as_ushort(h0)
                  | ((uint32_t)__bfloat16_as_ushort(h1) << 16);
            lp[e] = (uint32_t)__bfloat16_as_ushort(l0)
                  | ((uint32_t)__bfloat16_as_ushort(l1) << 16);
        }
    } else {
        #pragma unroll
        for (int e = 0; e < 4; e++) { hp[e] = 0u; lp[e] = 0u; }
    }
    *(uint4*)(dhi + off) = make_uint4(hp[0], hp[1], hp[2], hp[3]);
    *(uint4*)(dlo + off) = make_uint4(lp[0], lp[1], lp[2], lp[3]);
}

// ---------------------------------------------------------------------------
// GEMM [8320,768] x [512,768]^T, 3-term bf16 split, HMMA (R6/R15 structure,
// race-free 3-stage pipeline, XOR-swizzled smem). Unchanged from R15 (93.2us).
// ---------------------------------------------------------------------------
extern __shared__ __align__(128) char gsm[];

__global__ __launch_bounds__(256, 2) void gemm_mma_kernel(
    const float* __restrict__ bq, const float* __restrict__ bv)
{
    __shared__ float bias_s[NT_];
    const uint32_t smb = smem_u32(gsm);
    const int tid  = threadIdx.x;
    const int wid  = tid >> 5;
    const int lane = tid & 31;
    const int m0   = blockIdx.x * MT_;
    const int n0   = blockIdx.y * NT_;

    if (tid < NT_)
        bias_s[tid] = (n0 < DO_) ? bq[n0 + tid] : bv[n0 - DO_ + tid];

    const int lrow = tid >> 2;
    const int lc16 = tid & 3;
    const int lsel = (tid >> 3) & 3;
    const uint32_t d0 = (uint32_t)lrow * 64 + (uint32_t)((lc16 ^ lsel) & 3) * 16;
    const uint32_t d1 = d0 + 64 * 64;

    const size_t aoff0 = (size_t)(m0 + lrow) * D_ + lc16 * 8;
    const size_t aoff1 = aoff0 + (size_t)64 * D_;
    const size_t boff0 = (size_t)(n0 + lrow) * D_ + lc16 * 8;
    const size_t boff1 = boff0 + (size_t)64 * D_;

    #define ISSUE_CHUNK(c, s) do {                                   \
        uint32_t st = smb + (s) * STG_B_;                            \
        int kk = (c) * KC_;                                          \
        CPA16(st + AH_OFF_ + d0, g_ahi + aoff0 + kk);                \
        CPA16(st + AH_OFF_ + d1, g_ahi + aoff1 + kk);                \
        CPA16(st + AL_OFF_ + d0, g_alo + aoff0 + kk);                \
        CPA16(st + AL_OFF_ + d1, g_alo + aoff1 + kk);                \
        CPA16(st + BH_OFF_ + d0, g_bhi + boff0 + kk);                \
        CPA16(st + BH_OFF_ + d1, g_bhi + boff1 + kk);                \
        CPA16(st + BL_OFF_ + d0, g_blo + boff0 + kk);                \
        CPA16(st + BL_OFF_ + d1, g_blo + boff1 + kk);                \
        CPA_COMMIT();                                                \
    } while (0)

    const int mwarp = wid >> 2, nwarp = wid & 3;
    const int rowA = mwarp * 64 + (lane & 15);
    const int selA = (rowA >> 1) & 3;
    const int hiA  = lane >> 4;
    const uint32_t aRow = (uint32_t)rowA * 64;
    const uint32_t aS0  = (uint32_t)(((0 + hiA) ^ selA) & 3) * 16;
    const uint32_t aS1  = (uint32_t)(((2 + hiA) ^ selA) & 3) * 16;

    const int rowB = nwarp * 32 + (lane & 7) + ((lane >> 4) & 1) * 8;
    const int selB = (rowB >> 1) & 3;
    const int hiB  = (lane >> 3) & 1;
    const uint32_t bRow = (uint32_t)rowB * 64;
    const uint32_t bS0  = (uint32_t)(((0 + hiB) ^ selB) & 3) * 16;
    const uint32_t bS1  = (uint32_t)(((2 + hiB) ^ selB) & 3) * 16;

    float acc[4][4][4];
    #pragma unroll
    for (int mt = 0; mt < 4; mt++)
        #pragma unroll
        for (int nt = 0; nt < 4; nt++)
            #pragma unroll
            for (int e = 0; e < 4; e++) acc[mt][nt][e] = 0.f;

    ISSUE_CHUNK(0, 0);
    ISSUE_CHUNK(1, 1);

    int stg = 0;
    for (int c = 0; c < NCHUNK_; c++) {
        if (c < NCHUNK_ - 1) { CPA_WAIT(1); } else { CPA_WAIT(0); }
        __syncthreads();
        if (c + 2 < NCHUNK_) {
            int ns = stg + 2; if (ns >= NSTG_) ns -= NSTG_;
            ISSUE_CHUNK(c + 2, ns);
        }

        const uint32_t st = smb + stg * STG_B_;
        #pragma unroll
        for (int ks = 0; ks < 2; ks++) {
            const uint32_t aAdr = st + aRow + (ks ? aS1 : aS0);
            const uint32_t bAdr = st + bRow + (ks ? bS1 : bS0);

            uint32_t Ah[4][4], Bh[2][4], Al[4][4], Bl[2][4];
            #pragma unroll
            for (int mt = 0; mt < 4; mt++)
                LDMX4(Ah[mt][0], Ah[mt][1], Ah[mt][2], Ah[mt][3],
                      aAdr + AH_OFF_ + mt * 1024);
            #pragma unroll
            for (int pr = 0; pr < 2; pr++)
                LDMX4(Bh[pr][0], Bh[pr][1], Bh[pr][2], Bh[pr][3],
                      bAdr + BH_OFF_ + pr * 1024);
            #pragma unroll
            for (int mt = 0; mt < 4; mt++)
                #pragma unroll
                for (int nt = 0; nt < 4; nt++)
                    mma_bf16(acc[mt][nt], Ah[mt], &Bh[nt >> 1][(nt & 1) * 2]);

            #pragma unroll
            for (int mt = 0; mt < 4; mt++)
                LDMX4(Al[mt][0], Al[mt][1], Al[mt][2], Al[mt][3],
                      aAdr + AL_OFF_ + mt * 1024);
            #pragma unroll
            for (int mt = 0; mt < 4; mt++)
                #pragma unroll
                for (int nt = 0; nt < 4; nt++)
                    mma_bf16(acc[mt][nt], Al[mt], &Bh[nt >> 1][(nt & 1) * 2]);

            #pragma unroll
            for (int pr = 0; pr < 2; pr++)
                LDMX4(Bl[pr][0], Bl[pr][1], Bl[pr][2], Bl[pr][3],
                      bAdr + BL_OFF_ + pr * 1024);
            #pragma unroll
            for (int mt = 0; mt < 4; mt++)
                #pragma unroll
                for (int nt = 0; nt < 4; nt++)
                    mma_bf16(acc[mt][nt], Ah[mt], &Bl[nt >> 1][(nt & 1) * 2]);
        }
        if (++stg >= NSTG_) stg = 0;
    }

    // epilogue
    const int fg = lane >> 2;
    const int fc = (lane & 3) * 2;
    const int colbase = n0 + nwarp * 32;
    #pragma unroll
    for (int mt = 0; mt < 4; mt++) {
        #pragma unroll
        for (int rh = 0; rh < 2; rh++) {
            int r = m0 + mwarp * 64 + mt * 16 + fg + rh * 8;
            float* dst;
            bool add_bias;
            if (r < ROWS_) {
                dst = g_qv + (size_t)r * NQV_ + colbase;
                add_bias = true;
            } else if (r < MTOT_) {
                dst = g_pos + (size_t)(r - ROWS_) * NQV_ + colbase;
                add_bias = false;
            } else continue;
            #pragma unroll
            for (int nt = 0; nt < 4; nt++) {
                int cidx = nwarp * 32 + nt * 8 + fc;
                float2 o;
                o.x = acc[mt][nt][rh * 2];
                o.y = acc[mt][nt][rh * 2 + 1];
                if (add_bias) { o.x += bias_s[cidx]; o.y += bias_s[cidx + 1]; }
                *(float2*)(dst + nt * 8 + fc) = o;
            }
        }
    }
}

// ---------------------------------------------------------------------------
// Attn v4: t-PAIRED. Block = 128 t for one (b,h), 256 blocks = 1 wave at
// 2 CTAs/SM. Lane handles t-pair (tl, tl+1); warp covers 16 t in ONE pass
// (lane = 4*tsub + dg; tl = warp*16 + 2*tsub). Loop r=0..15 over the union
// of both windows: row tl+r serves (t0,w=r) and (t1,w=r-1) for scores AND
// context (same row!), halving k/v smem traffic.
// Layout: row stride 80 floats, per-row toggle offset ((row>>1)&1)*16,
// lane dg owns dims {4dg+16m, m=0..3} -> phase-conflict-free (see analysis).
// ---------------------------------------------------------------------------
#define RST_ 80
#define NTB_ 128                              // t per block
#define NROW_ (NTB_ + 2 * W1_)                // 142 rows
#define ATT_SMEM_ ((NROW_ * RST_ * 2 + W2_ * RST_ * 2) * 4)   // 100480 B

#define SOFF(row) ((row) * RST_ + (((row) >> 1) & 1) * 16)

extern __shared__ __align__(16) float asmf[];

__device__ __forceinline__ float dot4(float4 a, float4 b) {
    return a.x * b.x + a.y * b.y + a.z * b.z + a.w * b.w;
}
__device__ __forceinline__ float4 add4(float4 a, float4 b) {
    return make_float4(a.x + b.x, a.y + b.y, a.z + b.z, a.w + b.w);
}

__global__ __launch_bounds__(256) void attn_kernel(float* __restrict__ out) {
    float* ks = asmf;
    float* vs = ks + NROW_ * RST_;
    float* pq = vs + NROW_ * RST_;
    float* pv = pq + W2_ * RST_;

    const int bx    = blockIdx.x;             // 0..255
    const int chunk = bx & 31;
    const int h     = (bx >> 5) & 3;
    const int b     = bx >> 7;
    const int t0g   = chunk * NTB_;
    const int tid   = threadIdx.x;

    const size_t base_row = (size_t)b * TP_ + t0g;

    // loaders: idx -> (row, c4); dim-chunk c4 stores dims [4*c4, 4*c4+4) at
    // float offset (c4&3)*4 + (c4>>2)*16 within the row (matches compute map)
    for (int idx = tid; idx < NROW_ * 16; idx += 256) {
        int row = idx >> 4, c4 = idx & 15;
        int doff = SOFF(row) + (c4 & 3) * 4 + (c4 >> 2) * 16;
        const float* src = g_qv + (base_row + row) * NQV_ + h * DH_ + c4 * 4;
        *(float4*)(ks + doff) = *(const float4*)src;
        *(float4*)(vs + doff) = *(const float4*)(src + DO_);
    }
    for (int idx = tid; idx < W2_ * 16; idx += 256) {
        int row = idx >> 4, c4 = idx & 15;
        int doff = SOFF(row) + (c4 & 3) * 4 + (c4 >> 2) * 16;
        const float* src = g_pos + (size_t)row * NQV_ + h * DH_ + c4 * 4;
        *(float4*)(pq + doff) = *(const float4*)src;
        *(float4*)(pv + doff) = *(const float4*)(src + DO_);
    }
    __syncthreads();

    const int warp = tid >> 5;
    const int lane = tid & 31;
    const int tsub = lane >> 2;
    const int dg   = lane & 3;
    const int tl   = warp * 16 + tsub * 2;    // first t of pair, 0..126
    const int dgo  = dg * 4;                  // lane's dim chunks: dgo + m*16

    // q rows for the pair (absolute smem rows tl+W1, tl+1+W1)
    float4 q0[4], q1[4];
    {
        const float* q0p = ks + SOFF(tl + W1_) + dgo;
        const float* q1p = ks + SOFF(tl + 1 + W1_) + dgo;
        #pragma unroll
        for (int m = 0; m < 4; m++) {
            q0[m] = *(const float4*)(q0p + m * 16);
            q1[m] = *(const float4*)(q1p + m * 16);
        }
    }

    float4 a0[4], a1[4];
    #pragma unroll
    for (int m = 0; m < 4; m++) {
        a0[m] = make_float4(0.f, 0.f, 0.f, 0.f);
        a1[m] = make_float4(0.f, 0.f, 0.f, 0.f);
    }

    #pragma unroll
    for (int r = 0; r < 16; r++) {
        const float* krp = ks + SOFF(tl + r) + dgo;
        float4 kr[4];
        #pragma unroll
        for (int m = 0; m < 4; m++) kr[m] = *(const float4*)(krp + m * 16);

        float p0 = 0.f, p1 = 0.f;
        if (r < 15) {                        // t0, w = r
            const float* pqp = pq + SOFF(r) + dgo;
            #pragma unroll
            for (int m = 0; m < 4; m++)
                p0 += dot4(q0[m], add4(kr[m], *(const float4*)(pqp + m * 16)));
        }
        if (r >= 1) {                        // t1, w = r-1
            const float* pqp = pq + SOFF(r - 1) + dgo;
            #pragma unroll
            for (int m = 0; m < 4; m++)
                p1 += dot4(q1[m], add4(kr[m], *(const float4*)(pqp + m * 16)));
        }
        // reduce across the 4 dg lanes (bits 0-1 of lane)
        p0 += __shfl_xor_sync(0xffffffffu, p0, 1);
        p0 += __shfl_xor_sync(0xffffffffu, p0, 2);
        p1 += __shfl_xor_sync(0xffffffffu, p1, 1);
        p1 += __shfl_xor_sync(0xffffffffu, p1, 2);

        const float* vrp = vs + SOFF(tl + r) + dgo;
        float4 vr[4];
        #pragma unroll
        for (int m = 0; m < 4; m++) vr[m] = *(const float4*)(vrp + m * 16);

        if (r < 15) {
            const float* pvp = pv + SOFF(r) + dgo;
            #pragma unroll
            for (int m = 0; m < 4; m++) {
                float4 vv = add4(vr[m], *(const float4*)(pvp + m * 16));
                a0[m].x += p0 * vv.x; a0[m].y += p0 * vv.y;
                a0[m].z += p0 * vv.z; a0[m].w += p0 * vv.w;
            }
        }
        if (r >= 1) {
            const float* pvp = pv + SOFF(r - 1) + dgo;
            #pragma unroll
            for (int m = 0; m < 4; m++) {
                float4 vv = add4(vr[m], *(const float4*)(pvp + m * 16));
                a1[m].x += p1 * vv.x; a1[m].y += p1 * vv.y;
                a1[m].z += p1 * vv.z; a1[m].w += p1 * vv.w;
            }
        }
    }

    // write out: lane owns dims {dgo + m*16 .. +3} of head h for t0 and t1
    {
        float* d0 = out + ((size_t)b * T_ + t0g + tl) * DO_ + h * DH_ + dgo;
        float* d1 = d0 + DO_;   // t+1 is next row of out
        #pragma unroll
        for (int m = 0; m < 4; m++) {
            *(float4*)(d0 + m * 16) = a0[m];
            *(float4*)(d1 + m * 16) = a1[m];
        }
    }
}

// ---------------------------------------------------------------------------
extern "C" void kernel_launch(void* const* d_in, const int* in_sizes, int n_in,
                              void* d_out, int out_size) {
    const float* inputs  = (const float*)d_in[0];
    const float* Wq      = (const float*)d_in[1];
    const float* bq      = (const float*)d_in[2];
    const float* Wv      = (const float*)d_in[3];
    const float* bv      = (const float*)d_in[4];
    const float* pos_emb = (const float*)d_in[5];
    float* out = (float*)d_out;

    cudaFuncSetAttribute(gemm_mma_kernel,
                         cudaFuncAttributeMaxDynamicSharedMemorySize, GSMEM_);
    cudaFuncSetAttribute(attn_kernel,
                         cudaFuncAttributeMaxDynamicSharedMemorySize, ATT_SMEM_);

    prep_kernel<<<(NWV_ + NAV_ + 255) / 256, 256>>>(inputs, Wq, Wv, pos_emb);

    dim3 ggrid(MPAD_ / MT_, NQV_ / NT_);
    gemm_mma_kernel<<<ggrid, 256, GSMEM_>>>(bq, bv);

    attn_kernel<<<B_ * H_ * (T_ / NTB_), 256, ATT_SMEM_>>>(out);
}

// round 17
// speedup vs baseline: 1.9196x; 1.3009x over previous
#include <cuda_runtime.h>
#include <cuda_fp16.h>
#include <cstdint>

// Problem constants
#define B_   2
#define T_   4096
#define D_   768
#define DO_  256
#define H_   4
#define DH_  64
#define W1_  7
#define W2_  15
#define TP_  (T_ + 2*W1_)       // 4110
#define ROWS_ (B_ * TP_)        // 8220
#define MTOT_ (ROWS_ + W2_)     // 8235
#define MPAD_ 8320              // 65 * 128
#define NQV_ 512

#define MT_ 128
#define NT_ 128
#define KC_ 32                  // k per chunk
#define NCHUNK_ (D_ / KC_)      // 24

// smem stage: swizzled 64B rows, 3 arrays x 8KB:
//   AH=0, AL=8192, BH=16384 ; stage = 24576, 3 stages
#define AH_OFF_ 0
#define AL_OFF_ 8192
#define BH_OFF_ 16384
#define STG_B_ 24576
#define NSTG_ 3
#define GSMEM_ (NSTG_ * STG_B_)   // 73728

// Scratch
__device__ float g_qv[ROWS_ * NQV_];
__device__ float g_pos[W2_ * NQV_];
__device__ __half g_ahi[MPAD_ * D_];
__device__ __half g_alo[MPAD_ * D_];
__device__ __half g_bhi[NQV_ * D_];

// ---------------------------------------------------------------------------
__device__ __forceinline__ uint32_t smem_u32(const void* p) {
    uint32_t a;
    asm("{ .reg .u64 t; cvta.to.shared.u64 t, %1; cvt.u32.u64 %0, t; }"
        : "=r"(a) : "l"(p));
    return a;
}
#define CPA16(dst, src) \
    asm volatile("cp.async.ca.shared.global [%0], [%1], 16;" :: "r"(dst), "l"(src))
#define CPA_COMMIT() asm volatile("cp.async.commit_group;" ::: "memory")
#define CPA_WAIT(n)  asm volatile("cp.async.wait_group %0;" :: "n"(n) : "memory")
#define LDMX4(r0, r1, r2, r3, a) \
    asm volatile("ldmatrix.sync.aligned.m8n8.x4.shared.b16 {%0,%1,%2,%3}, [%4];" \
                 : "=r"(r0), "=r"(r1), "=r"(r2), "=r"(r3) : "r"(a))

__device__ __forceinline__ void mma_fp16(float* d, const uint32_t* a,
                                         const uint32_t* b) {
    asm volatile(
        "mma.sync.aligned.m16n8k16.row.col.f32.f16.f16.f32 "
        "{%0,%1,%2,%3}, {%4,%5,%6,%7}, {%8,%9}, {%0,%1,%2,%3};"
        : "+f"(d[0]), "+f"(d[1]), "+f"(d[2]), "+f"(d[3])
        : "r"(a[0]), "r"(a[1]), "r"(a[2]), "r"(a[3]), "r"(b[0]), "r"(b[1]));
}

// ---------------------------------------------------------------------------
// Prep: fp16 hi/lo split of activations (+pos, +zero pad); fp16 hi of weights.
// ---------------------------------------------------------------------------
#define NWV_ (NQV_ * (D_ / 8))          // 49152
#define NAV_ (MPAD_ * (D_ / 8))         // 798720
__global__ void prep_kernel(const float* __restrict__ inputs,
                            const float* __restrict__ Wq,
                            const float* __restrict__ Wv,
                            const float* __restrict__ pos_emb) {
    int i = blockIdx.x * blockDim.x + threadIdx.x;
    if (i < NWV_) {
        // weights: hi only
        int n = i / (D_ / 8);
        int k8 = (i - n * (D_ / 8)) * 8;
        const float* src = (n < DO_) ? Wq + (size_t)n * D_ + k8
                                     : Wv + (size_t)(n - DO_) * D_ + k8;
        float4 f0 = *(const float4*)src;
        float4 f1 = *(const float4*)(src + 4);
        float v[8] = {f0.x, f0.y, f0.z, f0.w, f1.x, f1.y, f1.z, f1.w};
        uint32_t hp[4];
        #pragma unroll
        for (int e = 0; e < 4; e++) {
            __half h0 = __float2half_rn(v[2*e]);
            __half h1 = __float2half_rn(v[2*e+1]);
            hp[e] = (uint32_t)__half_as_ushort(h0)
                  | ((uint32_t)__half_as_ushort(h1) << 16);
        }
        *(uint4*)(g_bhi + (size_t)n * D_ + k8) = make_uint4(hp[0], hp[1], hp[2], hp[3]);
    } else if (i < NWV_ + NAV_) {
        int j = i - NWV_;
        int r = j / (D_ / 8);
        int k8 = (j - r * (D_ / 8)) * 8;
        size_t off = (size_t)r * D_ + k8;
        const float* src = nullptr;
        if (r < ROWS_) {
            int bb = r / TP_;
            int tp = r - bb * TP_;
            if (tp >= W1_ && tp < W1_ + T_)
                src = inputs + ((size_t)bb * T_ + (tp - W1_)) * D_ + k8;
        } else if (r < MTOT_) {
            src = pos_emb + (size_t)(r - ROWS_) * D_ + k8;
        }
        uint32_t hp[4], lp[4];
        if (src) {
            float4 f0 = *(const float4*)src;
            float4 f1 = *(const float4*)(src + 4);
            float v[8] = {f0.x, f0.y, f0.z, f0.w, f1.x, f1.y, f1.z, f1.w};
            #pragma unroll
            for (int e = 0; e < 4; e++) {
                __half h0 = __float2half_rn(v[2*e]);
                __half h1 = __float2half_rn(v[2*e+1]);
                __half l0 = __float2half_rn(v[2*e]   - __half2float(h0));
                __half l1 = __float2half_rn(v[2*e+1] - __half2float(h1));
                hp[e] = (uint32_t)__half_as_ushort(h0)
                      | ((uint32_t)__half_as_ushort(h1) << 16);
                lp[e] = (uint32_t)__half_as_ushort(l0)
                      | ((uint32_t)__half_as_ushort(l1) << 16);
            }
        } else {
            #pragma unroll
            for (int e = 0; e < 4; e++) { hp[e] = 0u; lp[e] = 0u; }
        }
        *(uint4*)(g_ahi + off) = make_uint4(hp[0], hp[1], hp[2], hp[3]);
        *(uint4*)(g_alo + off) = make_uint4(lp[0], lp[1], lp[2], lp[3]);
    }
}

// ---------------------------------------------------------------------------
// GEMM [8320,768] x [512,768]^T, 2-term fp16 split (Ah*Bh + Al*Bh), HMMA.
// Race-free 3-stage cp.async pipeline (R6): wait(1) -> sync -> issue(c+2).
// XOR-swizzled smem (row*64B, slot = (c16 ^ (row>>1)) & 3).
// ---------------------------------------------------------------------------
extern __shared__ __align__(128) char gsm[];

__global__ __launch_bounds__(256, 2) void gemm_mma_kernel(
    const float* __restrict__ bq, const float* __restrict__ bv)
{
    __shared__ float bias_s[NT_];
    const uint32_t smb = smem_u32(gsm);
    const int tid  = threadIdx.x;
    const int wid  = tid >> 5;
    const int lane = tid & 31;
    const int m0   = blockIdx.x * MT_;
    const int n0   = blockIdx.y * NT_;

    if (tid < NT_)
        bias_s[tid] = (n0 < DO_) ? bq[n0 + tid] : bv[n0 - DO_ + tid];

    // ---- loader: thread -> (row = tid>>2, c16 = tid&3) and (+64 rows)
    const int lrow = tid >> 2;
    const int lc16 = tid & 3;
    const int lsel = (tid >> 3) & 3;
    const uint32_t d0 = (uint32_t)lrow * 64 + (uint32_t)((lc16 ^ lsel) & 3) * 16;
    const uint32_t d1 = d0 + 64 * 64;

    const size_t aoff0 = (size_t)(m0 + lrow) * D_ + lc16 * 8;
    const size_t aoff1 = aoff0 + (size_t)64 * D_;
    const size_t boff0 = (size_t)(n0 + lrow) * D_ + lc16 * 8;
    const size_t boff1 = boff0 + (size_t)64 * D_;

    #define ISSUE_CHUNK(c, s) do {                                   \
        uint32_t st = smb + (s) * STG_B_;                            \
        int kk = (c) * KC_;                                          \
        CPA16(st + AH_OFF_ + d0, g_ahi + aoff0 + kk);                \
        CPA16(st + AH_OFF_ + d1, g_ahi + aoff1 + kk);                \
        CPA16(st + AL_OFF_ + d0, g_alo + aoff0 + kk);                \
        CPA16(st + AL_OFF_ + d1, g_alo + aoff1 + kk);                \
        CPA16(st + BH_OFF_ + d0, g_bhi + boff0 + kk);                \
        CPA16(st + BH_OFF_ + d1, g_bhi + boff1 + kk);                \
        CPA_COMMIT();                                                \
    } while (0)

    // ---- fragment address components
    const int mwarp = wid >> 2, nwarp = wid & 3;
    const int rowA = mwarp * 64 + (lane & 15);
    const int selA = (rowA >> 1) & 3;
    const int hiA  = lane >> 4;
    const uint32_t aRow = (uint32_t)rowA * 64;
    const uint32_t aS0  = (uint32_t)(((0 + hiA) ^ selA) & 3) * 16;
    const uint32_t aS1  = (uint32_t)(((2 + hiA) ^ selA) & 3) * 16;

    const int rowB = nwarp * 32 + (lane & 7) + ((lane >> 4) & 1) * 8;
    const int selB = (rowB >> 1) & 3;
    const int hiB  = (lane >> 3) & 1;
    const uint32_t bRow = (uint32_t)rowB * 64;
    const uint32_t bS0  = (uint32_t)(((0 + hiB) ^ selB) & 3) * 16;
    const uint32_t bS1  = (uint32_t)(((2 + hiB) ^ selB) & 3) * 16;

    float acc[4][4][4];
    #pragma unroll
    for (int mt = 0; mt < 4; mt++)
        #pragma unroll
        for (int nt = 0; nt < 4; nt++)
            #pragma unroll
            for (int e = 0; e < 4; e++) acc[mt][nt][e] = 0.f;

    ISSUE_CHUNK(0, 0);
    ISSUE_CHUNK(1, 1);

    int stg = 0;
    for (int c = 0; c < NCHUNK_; c++) {
        if (c < NCHUNK_ - 1) { CPA_WAIT(1); } else { CPA_WAIT(0); }
        __syncthreads();
        if (c + 2 < NCHUNK_) {
            int ns = stg + 2; if (ns >= NSTG_) ns -= NSTG_;
            ISSUE_CHUNK(c + 2, ns);
        }

        const uint32_t st = smb + stg * STG_B_;
        #pragma unroll
        for (int ks = 0; ks < 2; ks++) {
            const uint32_t aAdr = st + aRow + (ks ? aS1 : aS0);
            const uint32_t bAdr = st + bRow + (ks ? bS1 : bS0);

            uint32_t Ah[4][4], Bh[2][4], Al[4][4];
            #pragma unroll
            for (int mt = 0; mt < 4; mt++)
                LDMX4(Ah[mt][0], Ah[mt][1], Ah[mt][2], Ah[mt][3],
                      aAdr + AH_OFF_ + mt * 1024);
            #pragma unroll
            for (int pr = 0; pr < 2; pr++)
                LDMX4(Bh[pr][0], Bh[pr][1], Bh[pr][2], Bh[pr][3],
                      bAdr + BH_OFF_ + pr * 1024);
            #pragma unroll
            for (int mt = 0; mt < 4; mt++)
                #pragma unroll
                for (int nt = 0; nt < 4; nt++)
                    mma_fp16(acc[mt][nt], Ah[mt], &Bh[nt >> 1][(nt & 1) * 2]);

            #pragma unroll
            for (int mt = 0; mt < 4; mt++)
                LDMX4(Al[mt][0], Al[mt][1], Al[mt][2], Al[mt][3],
                      aAdr + AL_OFF_ + mt * 1024);
            #pragma unroll
            for (int mt = 0; mt < 4; mt++)
                #pragma unroll
                for (int nt = 0; nt < 4; nt++)
                    mma_fp16(acc[mt][nt], Al[mt], &Bh[nt >> 1][(nt & 1) * 2]);
        }
        if (++stg >= NSTG_) stg = 0;
    }

    // epilogue
    const int fg = lane >> 2;
    const int fc = (lane & 3) * 2;
    const int colbase = n0 + nwarp * 32;
    #pragma unroll
    for (int mt = 0; mt < 4; mt++) {
        #pragma unroll
        for (int rh = 0; rh < 2; rh++) {
            int r = m0 + mwarp * 64 + mt * 16 + fg + rh * 8;
            float* dst;
            bool add_bias;
            if (r < ROWS_) {
                dst = g_qv + (size_t)r * NQV_ + colbase;
                add_bias = true;
            } else if (r < MTOT_) {
                dst = g_pos + (size_t)(r - ROWS_) * NQV_ + colbase;
                add_bias = false;
            } else continue;
            #pragma unroll
            for (int nt = 0; nt < 4; nt++) {
                int cidx = nwarp * 32 + nt * 8 + fc;
                float2 o;
                o.x = acc[mt][nt][rh * 2];
                o.y = acc[mt][nt][rh * 2 + 1];
                if (add_bias) { o.x += bias_s[cidx]; o.y += bias_s[cidx + 1]; }
                *(float2*)(dst + nt * 8 + fc) = o;
            }
        }
    }
}

// ---------------------------------------------------------------------------
// Attn v4 (R16-proven, 88.5us config): t-PAIRED. Block = 128 t for one (b,h),
// 256 blocks = 1 wave at 2 CTAs/SM. Lane handles t-pair (tl, tl+1); warp
// covers 16 t in one pass. Row stride 80 floats + per-row toggle*16.
// ---------------------------------------------------------------------------
#define RST_ 80
#define NTB_ 128                              // t per block
#define NROW_ (NTB_ + 2 * W1_)                // 142 rows
#define ATT_SMEM_ ((NROW_ * RST_ * 2 + W2_ * RST_ * 2) * 4)   // 100480 B

#define SOFF(row) ((row) * RST_ + (((row) >> 1) & 1) * 16)

extern __shared__ __align__(16) float asmf[];

__device__ __forceinline__ float dot4(float4 a, float4 b) {
    return a.x * b.x + a.y * b.y + a.z * b.z + a.w * b.w;
}
__device__ __forceinline__ float4 add4(float4 a, float4 b) {
    return make_float4(a.x + b.x, a.y + b.y, a.z + b.z, a.w + b.w);
}

__global__ __launch_bounds__(256) void attn_kernel(float* __restrict__ out) {
    float* ks = asmf;
    float* vs = ks + NROW_ * RST_;
    float* pq = vs + NROW_ * RST_;
    float* pv = pq + W2_ * RST_;

    const int bx    = blockIdx.x;             // 0..255
    const int chunk = bx & 31;
    const int h     = (bx >> 5) & 3;
    const int b     = bx >> 7;
    const int t0g   = chunk * NTB_;
    const int tid   = threadIdx.x;

    const size_t base_row = (size_t)b * TP_ + t0g;

    for (int idx = tid; idx < NROW_ * 16; idx += 256) {
        int row = idx >> 4, c4 = idx & 15;
        int doff = SOFF(row) + (c4 & 3) * 4 + (c4 >> 2) * 16;
        const float* src = g_qv + (base_row + row) * NQV_ + h * DH_ + c4 * 4;
        *(float4*)(ks + doff) = *(const float4*)src;
        *(float4*)(vs + doff) = *(const float4*)(src + DO_);
    }
    for (int idx = tid; idx < W2_ * 16; idx += 256) {
        int row = idx >> 4, c4 = idx & 15;
        int doff = SOFF(row) + (c4 & 3) * 4 + (c4 >> 2) * 16;
        const float* src = g_pos + (size_t)row * NQV_ + h * DH_ + c4 * 4;
        *(float4*)(pq + doff) = *(const float4*)src;
        *(float4*)(pv + doff) = *(const float4*)(src + DO_);
    }
    __syncthreads();

    const int warp = tid >> 5;
    const int lane = tid & 31;
    const int tsub = lane >> 2;
    const int dg   = lane & 3;
    const int tl   = warp * 16 + tsub * 2;    // first t of pair, 0..126
    const int dgo  = dg * 4;                  // lane's dim chunks: dgo + m*16

    float4 q0[4], q1[4];
    {
        const float* q0p = ks + SOFF(tl + W1_) + dgo;
        const float* q1p = ks + SOFF(tl + 1 + W1_) + dgo;
        #pragma unroll
        for (int m = 0; m < 4; m++) {
            q0[m] = *(const float4*)(q0p + m * 16);
            q1[m] = *(const float4*)(q1p + m * 16);
        }
    }

    float4 a0[4], a1[4];
    #pragma unroll
    for (int m = 0; m < 4; m++) {
        a0[m] = make_float4(0.f, 0.f, 0.f, 0.f);
        a1[m] = make_float4(0.f, 0.f, 0.f, 0.f);
    }

    #pragma unroll
    for (int r = 0; r < 16; r++) {
        const float* krp = ks + SOFF(tl + r) + dgo;
        float4 kr[4];
        #pragma unroll
        for (int m = 0; m < 4; m++) kr[m] = *(const float4*)(krp + m * 16);

        float p0 = 0.f, p1 = 0.f;
        if (r < 15) {
            const float* pqp = pq + SOFF(r) + dgo;
            #pragma unroll
            for (int m = 0; m < 4; m++)
                p0 += dot4(q0[m], add4(kr[m], *(const float4*)(pqp + m * 16)));
        }
        if (r >= 1) {
            const float* pqp = pq + SOFF(r - 1) + dgo;
            #pragma unroll
            for (int m = 0; m < 4; m++)
                p1 += dot4(q1[m], add4(kr[m], *(const float4*)(pqp + m * 16)));
        }
        p0 += __shfl_xor_sync(0xffffffffu, p0, 1);
        p0 += __shfl_xor_sync(0xffffffffu, p0, 2);
        p1 += __shfl_xor_sync(0xffffffffu, p1, 1);
        p1 += __shfl_xor_sync(0xffffffffu, p1, 2);

        const float* vrp = vs + SOFF(tl + r) + dgo;
        float4 vr[4];
        #pragma unroll
        for (int m = 0; m < 4; m++) vr[m] = *(const float4*)(vrp + m * 16);

        if (r < 15) {
            const float* pvp = pv + SOFF(r) + dgo;
            #pragma unroll
            for (int m = 0; m < 4; m++) {
                float4 vv = add4(vr[m], *(const float4*)(pvp + m * 16));
                a0[m].x += p0 * vv.x; a0[m].y += p0 * vv.y;
                a0[m].z += p0 * vv.z; a0[m].w += p0 * vv.w;
            }
        }
        if (r >= 1) {
            const float* pvp = pv + SOFF(r - 1) + dgo;
            #pragma unroll
            for (int m = 0; m < 4; m++) {
                float4 vv = add4(vr[m], *(const float4*)(pvp + m * 16));
                a1[m].x += p1 * vv.x; a1[m].y += p1 * vv.y;
                a1[m].z += p1 * vv.z; a1[m].w += p1 * vv.w;
            }
        }
    }

    {
        float* d0 = out + ((size_t)b * T_ + t0g + tl) * DO_ + h * DH_ + dgo;
        float* d1 = d0 + DO_;
        #pragma unroll
        for (int m = 0; m < 4; m++) {
            *(float4*)(d0 + m * 16) = a0[m];
            *(float4*)(d1 + m * 16) = a1[m];
        }
    }
}

// ---------------------------------------------------------------------------
extern "C" void kernel_launch(void* const* d_in, const int* in_sizes, int n_in,
                              void* d_out, int out_size) {
    const float* inputs  = (const float*)d_in[0];
    const float* Wq      = (const float*)d_in[1];
    const float* bq      = (const float*)d_in[2];
    const float* Wv      = (const float*)d_in[3];
    const float* bv      = (const float*)d_in[4];
    const float* pos_emb = (const float*)d_in[5];
    float* out = (float*)d_out;

    cudaFuncSetAttribute(gemm_mma_kernel,
                         cudaFuncAttributeMaxDynamicSharedMemorySize, GSMEM_);
    cudaFuncSetAttribute(attn_kernel,
                         cudaFuncAttributeMaxDynamicSharedMemorySize, ATT_SMEM_);

    prep_kernel<<<(NWV_ + NAV_ + 255) / 256, 256>>>(inputs, Wq, Wv, pos_emb);

    dim3 ggrid(MPAD_ / MT_, NQV_ / NT_);
    gemm_mma_kernel<<<ggrid, 256, GSMEM_>>>(bq, bv);

    attn_kernel<<<B_ * H_ * (T_ / NTB_), 256, ATT_SMEM_>>>(out);
}